// round 16
// baseline (speedup 1.0000x reference)
#include <cuda_runtime.h>
#include <cuda_bf16.h>

typedef unsigned long long ULL;

#define NB 32        // batch
#define NS 256       // seq len
#define NE 256       // emb
#define NH 512       // hidden
#define NT 45        // tags
#define NG 2048      // 4*NH

// ---------------- scratch (static device globals: allowed) ----------------
__device__ float g_embeds[NS * NB * NE];           // [s][b][e]     8 MB
__device__ float g_xp[2 * NS * NG * NB];           // [dir][s][j][b] 128 MB
__device__ float g_hs[2 * NS * NB * NH];           // [dir][s][b][k] 32 MB
__device__ float g_em[NB * NS * NT];               // [b][s][t]
__device__ float g_loss[NB];
__device__ unsigned g_flag[2][64 * 32];            // per-CTA step flags, 128B padded

// ---------------- f32x2 packed FMA ----------------
__device__ __forceinline__ void fma2(ULL &d, ULL a, ULL b) {
    asm("fma.rn.f32x2 %0, %1, %2, %0;" : "+l"(d) : "l"(a), "l"(b));
}
union F4U { float4 f; ULL u[2]; };
union F2U { ULL u; float2 f; };

// ============================================================
// Kernel 1: embedding gather.  grid 8192, block 64
// ============================================================
__global__ void k_gather(const int* __restrict__ x, const float* __restrict__ emb) {
    int row = blockIdx.x;                 // row = s*32 + b
    int s = row >> 5, b = row & 31;
    int tok = x[b * NS + s];
    const float4* src = reinterpret_cast<const float4*>(emb) + tok * (NE / 4);
    float4* dst = reinterpret_cast<float4*>(g_embeds) + row * (NE / 4);
    dst[threadIdx.x] = src[threadIdx.x];
}

// ============================================================
// Kernel 2: input projection GEMM (+bias), broadcast-w tiling.
// xp[dir][s][j][b] = sum_e w_ih[dir][j][e]*embeds[s][b][e] + bias[j]
// grid (16, 256, 2), block 256. CTA tile 128j x 32b, K staged in 4 chunks.
// Warp = 16 j-rows (uniform/broadcast), lane = batch. acc[16] across full K.
// ============================================================
__global__ __launch_bounds__(256) void k_inproj(
    const float* __restrict__ w_f, const float* __restrict__ bias_f,
    const float* __restrict__ w_b, const float* __restrict__ bias_b)
{
    __shared__ float4 sW4[128 * 17];
    __shared__ float4 sX4[32 * 17];
    const int jb  = blockIdx.x * 128;
    const int s   = blockIdx.y;
    const int dir = blockIdx.z;
    const float* W    = dir ? w_b : w_f;
    const float* bias = dir ? bias_b : bias_f;
    const int tid  = threadIdx.x;
    const int wid  = tid >> 5;          // warp: rows jb + wid*16 .. +15
    const int lane = tid & 31;          // batch

    const float4* Wg = reinterpret_cast<const float4*>(W);
    const float4* Xg = reinterpret_cast<const float4*>(g_embeds);

    ULL acc[16] = {};
    for (int kt = 0; kt < 4; ++kt) {
        #pragma unroll
        for (int i = 0; i < 8; ++i) {
            int idx = tid + 256 * i;
            int r = idx >> 4, c = idx & 15;
            sW4[r * 17 + c] = Wg[(jb + r) * 64 + kt * 16 + c];
        }
        #pragma unroll
        for (int i = 0; i < 2; ++i) {
            int idx = tid + 256 * i;
            int r = idx >> 4, c = idx & 15;
            sX4[r * 17 + c] = Xg[(s * 32 + r) * 64 + kt * 16 + c];
        }
        __syncthreads();
        const float4* xb = sX4 + lane * 17;
        const float4* wb = sW4 + (wid * 16) * 17;
        #pragma unroll 2
        for (int k4 = 0; k4 < 16; ++k4) {
            F4U h; h.f = xb[k4];
            #pragma unroll
            for (int r = 0; r < 16; ++r) {
                F4U w; w.f = wb[r * 17 + k4];       // uniform addr -> broadcast
                fma2(acc[r], w.u[0], h.u[0]);
                fma2(acc[r], w.u[1], h.u[1]);
            }
        }
        __syncthreads();
    }
    #pragma unroll
    for (int r = 0; r < 16; ++r) {
        int j = jb + wid * 16 + r;
        F2U a; a.u = acc[r];
        g_xp[((dir * NS + s) * NG + j) * NB + lane] = a.f.x + a.f.y + bias[j];
    }
}

// ============================================================
// Kernel 3: persistent bidirectional LSTM recurrence.
// grid 128 (64 CTAs/dir, each owns 8 hidden units = 32 gate rows),
// block 256, dyn smem 148992 B -> 1 CTA/SM, all co-resident.
// Dot phase: warp = (16 rows x K-quarter), lane = batch; w loads are
// uniform-address broadcasts (1 wf), h loads per-lane conflict-free.
// Flag-array barrier; h exchanged via g_hs; cell state in regs.
// ============================================================
__global__ __launch_bounds__(256, 1) void k_lstm(
    const float* __restrict__ whh_f, const float* __restrict__ whh_b)
{
    extern __shared__ float sm[];
    float* sW = sm;               // 32 rows x 516 floats (pitch 129 float4)
    float* sH = sm + 16512;       // 32 x 516
    float* sP = sm + 33024;       // 4 x 32 x 33 = 4224
    const int tid = threadIdx.x;
    const int dir = blockIdx.x >> 6;
    const int d   = blockIdx.x & 63;
    const int u0  = d * 8;
    const float* W = dir ? whh_b : whh_f;

    // load this CTA's 32 gate rows of w_hh into smem (resident all 256 steps)
    {
        const float4* Wg = reinterpret_cast<const float4*>(W);
        float4* sW4 = reinterpret_cast<float4*>(sW);
        for (int idx = tid; idx < 32 * 128; idx += 256) {
            int r = idx >> 7, k4 = idx & 127;
            int grow = ((r >> 3) << 9) + u0 + (r & 7);
            sW4[r * 129 + k4] = Wg[grow * 128 + k4];
        }
    }
    for (int idx = tid; idx < 32 * 516; idx += 256) sH[idx] = 0.f;
    __shared__ unsigned s_base;
    if (tid == 0) s_base = *(volatile unsigned*)&g_flag[dir][d * 32];
    __syncthreads();
    const unsigned base_gen = s_base;

    // dot-phase mapping: warp -> (K-group, row-half); lane -> batch
    const int wid  = tid >> 5;
    const int lane = tid & 31;
    const int g    = wid & 3;            // K-quarter
    const int rh   = (wid >> 2) * 16;    // row base: 0 or 16
    const int k4b  = g * 32;
    // fused combine+cell mapping: batch cb (coalesced), unit ui
    const int cb = tid & 31;
    const int ui = tid >> 5;

    float4* sW4 = reinterpret_cast<float4*>(sW);
    float4* sH4 = reinterpret_cast<float4*>(sH);

    float c_reg = 0.f;            // persistent cell state for (ui, cb)

    for (int step = 0; step < NS; ++step) {
        const int ts = dir ? (NS - 1 - step) : step;

        // prefetch xp for the 4 gates of (ui, cb); consumed after dot phase
        const float* xpb = g_xp + (dir * NS + ts) * NG * NB;
        float xgi = xpb[(u0 + ui) * NB + cb];
        float xgf = xpb[(512 + u0 + ui) * NB + cb];
        float xgg = xpb[(1024 + u0 + ui) * NB + cb];
        float xgo = xpb[(1536 + u0 + ui) * NB + cb];

        if (step > 0) {
            const int tp = dir ? (ts + 1) : (ts - 1);
            const float4* Hg = reinterpret_cast<const float4*>(g_hs)
                             + (ULL)(dir * NS + tp) * 32 * 128;
            for (int idx = tid; idx < 32 * 128; idx += 256) {
                int b = idx >> 7, k4 = idx & 127;
                sH4[b * 129 + k4] = Hg[b * 128 + k4];
            }
        }
        __syncthreads();

        // dot: 16 rows x own batch over this warp's K quarter
        {
            const float4* hb = sH4 + lane * 129 + k4b;
            const float4* wb = sW4 + rh * 129 + k4b;
            ULL acc[16] = {};
            #pragma unroll 2
            for (int k4 = 0; k4 < 32; ++k4) {
                F4U h; h.f = hb[k4];
                #pragma unroll
                for (int r = 0; r < 16; ++r) {
                    F4U w; w.f = wb[r * 129 + k4];   // uniform addr -> broadcast
                    fma2(acc[r], w.u[0], h.u[0]);
                    fma2(acc[r], w.u[1], h.u[1]);
                }
            }
            #pragma unroll
            for (int r = 0; r < 16; ++r) {
                F2U t; t.u = acc[r];
                sP[(g * 32 + rh + r) * 33 + lane] = t.f.x + t.f.y;
            }
        }
        __syncthreads();

        // fused combine + LSTM cell for (ui, cb)
        {
            float gi = xgi, gf = xgf, gg = xgg, go = xgo;
            #pragma unroll
            for (int q = 0; q < 4; ++q) {
                gi += sP[(q * 32 +      ui) * 33 + cb];
                gf += sP[(q * 32 +  8 + ui) * 33 + cb];
                gg += sP[(q * 32 + 16 + ui) * 33 + cb];
                go += sP[(q * 32 + 24 + ui) * 33 + cb];
            }
            float si = 1.f / (1.f + __expf(-gi));
            float sf = 1.f / (1.f + __expf(-gf));
            float so = 1.f / (1.f + __expf(-go));
            c_reg = sf * c_reg + si * tanhf(gg);
            float hv = so * tanhf(c_reg);
            g_hs[((ULL)(dir * NS + ts) * 32 + cb) * NH + u0 + ui] = hv;
        }
        __syncthreads();

        // flag-array barrier: parallel arrival, parallel polling
        const unsigned tgt = base_gen + (unsigned)step + 1u;
        if (tid == 0) {
            __threadfence();                       // cumulative release
            *(volatile unsigned*)&g_flag[dir][d * 32] = tgt;
        }
        if (tid < 64) {
            while (*(volatile unsigned*)&g_flag[dir][tid * 32] < tgt) {}
            __threadfence();                       // acquire
        }
        __syncthreads();
    }
}

// ============================================================
// Kernel 4: emissions GEMM: em[row][t] = H[row][1024] . lin_w[t][1024] + b
// grid 128 (64 rows each), block 256, smem-tiled, (4x4) register tile.
// ============================================================
__global__ __launch_bounds__(256, 1) void k_emis(
    const float* __restrict__ lin_w, const float* __restrict__ lin_b)
{
    extern __shared__ float es[];
    float* sH = es;                 // 64 rows x 260 floats (pitch 65 float4)
    float* sW = es + 16640;         // 48 rows x 260
    float4* sH4 = reinterpret_cast<float4*>(sH);
    float4* sW4 = reinterpret_cast<float4*>(sW);
    const int tid = threadIdx.x;
    const int R0 = blockIdx.x * 64;
    const int rt = tid & 15;        // rows rt + 16i
    const int tt = tid >> 4;        // tags tt + 12j (active tt<12)

    ULL acc[4][4] = {};             // [i: row][j: tag]
    for (int kt = 0; kt < 4; ++kt) {
        const int dirq = kt >> 1;
        const int koff = (kt & 1) * 64;
        const float4* Hg = reinterpret_cast<const float4*>(g_hs);
        #pragma unroll
        for (int i = 0; i < 16; ++i) {
            int idx = tid + 256 * i;
            int r = idx >> 6, c = idx & 63;
            int row = R0 + r, s = row >> 5, b = row & 31;
            sH4[r * 65 + c] = Hg[((dirq * NS + s) * 32 + b) * 128 + koff + c];
        }
        const float4* Wg = reinterpret_cast<const float4*>(lin_w);
        #pragma unroll
        for (int i = 0; i < 12; ++i) {
            int idx = tid + 256 * i;
            int r = idx >> 6, c = idx & 63;
            float4 v = make_float4(0.f, 0.f, 0.f, 0.f);
            if (r < NT) v = Wg[r * 256 + kt * 64 + c];
            sW4[r * 65 + c] = v;
        }
        __syncthreads();
        if (tt < 12) {
            const float4* hp0 = sH4 + (rt     ) * 65;
            const float4* hp1 = sH4 + (rt + 16) * 65;
            const float4* hp2 = sH4 + (rt + 32) * 65;
            const float4* hp3 = sH4 + (rt + 48) * 65;
            const float4* wp0 = sW4 + (tt     ) * 65;
            const float4* wp1 = sW4 + (tt + 12) * 65;
            const float4* wp2 = sW4 + (tt + 24) * 65;
            const float4* wp3 = sW4 + (tt + 36) * 65;
            #pragma unroll 4
            for (int k4 = 0; k4 < 64; ++k4) {
                F4U h[4], w[4];
                h[0].f = hp0[k4]; h[1].f = hp1[k4]; h[2].f = hp2[k4]; h[3].f = hp3[k4];
                w[0].f = wp0[k4]; w[1].f = wp1[k4]; w[2].f = wp2[k4]; w[3].f = wp3[k4];
                #pragma unroll
                for (int i = 0; i < 4; ++i)
                    #pragma unroll
                    for (int j = 0; j < 4; ++j) {
                        fma2(acc[i][j], h[i].u[0], w[j].u[0]);
                        fma2(acc[i][j], h[i].u[1], w[j].u[1]);
                    }
            }
        }
        __syncthreads();
    }
    if (tt < 12) {
        #pragma unroll
        for (int i = 0; i < 4; ++i) {
            int row = R0 + rt + 16 * i;
            int s = row >> 5, b = row & 31;
            #pragma unroll
            for (int j = 0; j < 4; ++j) {
                int t = tt + 12 * j;
                if (t < NT) {
                    F2U u; u.u = acc[i][j];
                    g_em[(b * NS + s) * NT + t] = u.f.x + u.f.y + lin_b[t];
                }
            }
        }
    }
}

// ============================================================
// Kernel 5: CRF forward algorithm + gold score.  grid 32, block 64
// ============================================================
__global__ void k_crf(const int* __restrict__ tags,
                      const float* __restrict__ start_t,
                      const float* __restrict__ end_t,
                      const float* __restrict__ trans)
{
    __shared__ float tr[NT * NT];
    __shared__ float al[2][48];
    __shared__ float red[64];
    __shared__ float s_score;
    const int b = blockIdx.x, tid = threadIdx.x;
    for (int i = tid; i < NT * NT; i += 64) tr[i] = trans[i];
    const float* em = g_em + b * NS * NT;
    const int* tg = tags + b * NS;

    float sc = 0.f;
    for (int s = tid; s < NS; s += 64) {
        int t = tg[s];
        sc += em[s * NT + t];
        if (s > 0) sc += trans[tg[s - 1] * NT + t];
    }
    red[tid] = sc;
    __syncthreads();
    if (tid == 0) {
        float tot = 0.f;
        for (int i = 0; i < 64; ++i) tot += red[i];
        tot += start_t[tg[0]] + end_t[tg[NS - 1]];
        s_score = tot;
    }
    if (tid < NT) al[0][tid] = start_t[tid] + em[tid];
    __syncthreads();

    int cur = 0;
    for (int s = 1; s < NS; ++s) {
        if (tid < NT) {
            const float* ao = al[cur];
            float m0 = -1e30f, m1 = -1e30f, m2 = -1e30f, m3 = -1e30f;
            #pragma unroll
            for (int j = 0; j < 44; j += 4) {
                m0 = fmaxf(m0, ao[j    ] + tr[(j    ) * NT + tid]);
                m1 = fmaxf(m1, ao[j + 1] + tr[(j + 1) * NT + tid]);
                m2 = fmaxf(m2, ao[j + 2] + tr[(j + 2) * NT + tid]);
                m3 = fmaxf(m3, ao[j + 3] + tr[(j + 3) * NT + tid]);
            }
            m0 = fmaxf(m0, ao[44] + tr[44 * NT + tid]);
            float m = fmaxf(fmaxf(m0, m1), fmaxf(m2, m3));
            float s0 = 0.f, s1 = 0.f, s2 = 0.f, s3 = 0.f;
            #pragma unroll
            for (int j = 0; j < 44; j += 4) {
                s0 += __expf(ao[j    ] + tr[(j    ) * NT + tid] - m);
                s1 += __expf(ao[j + 1] + tr[(j + 1) * NT + tid] - m);
                s2 += __expf(ao[j + 2] + tr[(j + 2) * NT + tid] - m);
                s3 += __expf(ao[j + 3] + tr[(j + 3) * NT + tid] - m);
            }
            s0 += __expf(ao[44] + tr[44 * NT + tid] - m);
            float sum = (s0 + s1) + (s2 + s3);
            al[cur ^ 1][tid] = m + __logf(sum) + em[s * NT + tid];
        }
        cur ^= 1;
        __syncthreads();
    }
    if (tid == 0) {
        float m = -1e30f;
        for (int t = 0; t < NT; ++t) m = fmaxf(m, al[cur][t] + end_t[t]);
        float sum = 0.f;
        for (int t = 0; t < NT; ++t) sum += __expf(al[cur][t] + end_t[t] - m);
        float logZ = m + __logf(sum);
        g_loss[b] = logZ - s_score;
    }
}

// ============================================================
// Kernel 6: deterministic fixed-order mean
// ============================================================
__global__ void k_final(float* out) {
    if (threadIdx.x == 0) {
        float t = 0.f;
        for (int b = 0; b < NB; ++b) t += g_loss[b];
        out[0] = t * (1.f / (float)NB);
    }
}

// ============================================================
extern "C" void kernel_launch(void* const* d_in, const int* in_sizes, int n_in,
                              void* d_out, int out_size) {
    const int*   x       = (const int*)d_in[0];
    const int*   tags    = (const int*)d_in[1];
    const float* emb     = (const float*)d_in[2];
    const float* w_ih_f  = (const float*)d_in[3];
    const float* w_hh_f  = (const float*)d_in[4];
    const float* b_f     = (const float*)d_in[5];
    const float* w_ih_b  = (const float*)d_in[6];
    const float* w_hh_b  = (const float*)d_in[7];
    const float* b_b     = (const float*)d_in[8];
    const float* lin_w   = (const float*)d_in[9];
    const float* lin_b   = (const float*)d_in[10];
    const float* start_t = (const float*)d_in[11];
    const float* end_t   = (const float*)d_in[12];
    const float* trans   = (const float*)d_in[13];
    float* out = (float*)d_out;
    (void)in_sizes; (void)n_in; (void)out_size;

    cudaFuncSetAttribute(k_lstm, cudaFuncAttributeMaxDynamicSharedMemorySize, 148992);
    cudaFuncSetAttribute(k_emis, cudaFuncAttributeMaxDynamicSharedMemorySize, 116480);

    k_gather<<<NS * NB, 64>>>(x, emb);
    k_inproj<<<dim3(16, NS, 2), 256>>>(w_ih_f, b_f, w_ih_b, b_b);
    k_lstm<<<128, 256, 148992>>>(w_hh_f, w_hh_b);
    k_emis<<<128, 256, 116480>>>(lin_w, lin_b);
    k_crf<<<NB, 64>>>(tags, start_t, end_t, trans);
    k_final<<<1, 32>>>(out);
}